// round 13
// baseline (speedup 1.0000x reference)
#include <cuda_runtime.h>
#include <math.h>

#define BSZ    4096
#define D      200
#define WIN    400     // 2*D
#define OC     32
#define FW     9
#define WOUT   392
#define FCLEN  12544   // OC*WOUT
#define FC1LEN 288     // OC*FW
#define EPSV   1e-5f

#define BB     16      // batch rows per block
#define XSTR   404     // padded x row stride (floats, mult of 4)
#define WSTR   204     // padded fc1_w tile stride

// scratch (no cudaMalloc allowed)
__device__ float d_g[WIN];          // g[m] = fc2_w[m]*s2[m]
__device__ float d_vT[WOUT * OC];   // vT[w*32+o] = v[o*392+w]
__device__ float d_s1[OC];
__device__ float d_t1[OC];
__device__ float d_sc[4];           // s0, t0, Cbase, Cadd

// ---------------------------------------------------------------------------
// prep_g: per-feature constants + scalar constant Cbase
// ---------------------------------------------------------------------------
__global__ void prep_g(const float* __restrict__ fc2_w,
                       const float* __restrict__ g2, const float* __restrict__ b2,
                       const float* __restrict__ m2, const float* __restrict__ v2,
                       const float* __restrict__ fc_b, const float* __restrict__ fc2_b,
                       const float* __restrict__ g1, const float* __restrict__ b1,
                       const float* __restrict__ m1, const float* __restrict__ v1,
                       const float* __restrict__ g0, const float* __restrict__ b0,
                       const float* __restrict__ m0, const float* __restrict__ v0)
{
    __shared__ float red[512];
    int t = threadIdx.x;
    float cp = 0.f;
    if (t < WIN) {
        float s2 = g2[t] * rsqrtf(v2[t] + EPSV);
        d_g[t] = fc2_w[t] * s2;
        cp = fc2_w[t] * (s2 * (fc_b[t] - m2[t]) + b2[t]);
    }
    if (t < OC) {
        float s1 = g1[t] * rsqrtf(v1[t] + EPSV);
        d_s1[t] = s1;
        d_t1[t] = b1[t] - s1 * m1[t];
    }
    if (t == 0) {
        float s0 = g0[0] * rsqrtf(v0[0] + EPSV);
        d_sc[0] = s0;
        d_sc[1] = b0[0] - s0 * m0[0];
    }
    red[t] = cp;
    __syncthreads();
    for (int s = 256; s > 0; s >>= 1) {
        if (t < s) red[t] += red[t + s];
        __syncthreads();
    }
    if (t == 0) d_sc[2] = red[0] + fc2_b[0];
}

// ---------------------------------------------------------------------------
// prep_v: v[i] = sum_m g[m]*fc_w[m,i]; store transposed vT[w*32+o]
// ---------------------------------------------------------------------------
__global__ void prep_v(const float* __restrict__ fc_w)
{
    __shared__ float gs[WIN];
    int t = threadIdx.x;
    for (int m = t; m < WIN; m += 256) gs[m] = d_g[m];
    __syncthreads();
    int i = blockIdx.x * 256 + t;   // 49*256 == 12544 exactly
    float a0 = 0.f, a1 = 0.f, a2 = 0.f, a3 = 0.f;
    const float* p = fc_w + i;
    #pragma unroll 4
    for (int m = 0; m < WIN; m += 4) {
        a0 += gs[m]     * p[(m)     * FCLEN];
        a1 += gs[m + 1] * p[(m + 1) * FCLEN];
        a2 += gs[m + 2] * p[(m + 2) * FCLEN];
        a3 += gs[m + 3] * p[(m + 3) * FCLEN];
    }
    float acc = (a0 + a1) + (a2 + a3);
    int o = i / WOUT;
    int w = i - o * WOUT;
    d_vT[w * OC + o] = acc;
}

// ---------------------------------------------------------------------------
// prep_c: Cadd = sum_{o,w} v[o,w]*t1[o]
// ---------------------------------------------------------------------------
__global__ void prep_c()
{
    __shared__ float red[512];
    int t = threadIdx.x;
    float p = 0.f;
    for (int j = t; j < WOUT * OC; j += 512)
        p += d_vT[j] * d_t1[j & 31];
    red[t] = p;
    __syncthreads();
    for (int s = 256; s > 0; s >>= 1) {
        if (t < s) red[t] += red[t + s];
        __syncthreads();
    }
    if (t == 0) d_sc[3] = red[0];
}

// ---------------------------------------------------------------------------
// main: gather -> k' GEMM (shared-staged) -> fused conv/contraction -> tanh
// ---------------------------------------------------------------------------
__global__ __launch_bounds__(256) void main_kernel(
    const int* __restrict__ e1_idx, const int* __restrict__ r_idx,
    const int* __restrict__ e2_idx,
    const float* __restrict__ Etab, const float* __restrict__ Rtab,
    const float* __restrict__ fc1_w, const float* __restrict__ fc1_b,
    const float* __restrict__ bias, float* __restrict__ out)
{
    extern __shared__ float sm[];
    float* xs = sm;                        // [BB][XSTR]
    float* rs = xs + BB * XSTR;            // [BB][200]
    float* ws = rs + BB * 200;             // [32][WSTR]
    float* ks = ws + 32 * WSTR;            // [BB][288]

    int t = threadIdx.x;
    int lane = t & 31, wid = t >> 5;
    int b0 = blockIdx.x * BB;

    float s0 = d_sc[0], t0 = d_sc[1];

    // gather x = s0*concat(e1,e2)+t0
    for (int idx = t; idx < BB * WIN; idx += 256) {
        int bb = idx / WIN, p = idx - bb * WIN;
        int b = b0 + bb;
        int row = (p < D) ? e1_idx[b] : e2_idx[b];
        int col = (p < D) ? p : p - D;
        xs[bb * XSTR + p] = s0 * Etab[row * D + col] + t0;
    }
    // gather r
    for (int idx = t; idx < BB * D; idx += 256) {
        int bb = idx / D, c = idx - bb * D;
        rs[bb * D + c] = Rtab[r_idx[b0 + bb] * D + c];
    }
    __syncthreads();

    // ---- Phase B: ks[bb][oj] = s1[o]*(r[bb]·fc1_w[oj] + fc1_b[oj]) ----
    int bbA = wid * 2, bbB = wid * 2 + 1;
    for (int tile = 0; tile < 9; tile++) {
        for (int q = t; q < 32 * 50; q += 256) {
            int rrow = q / 50, cq = q - rrow * 50;
            float4 w4 = *(const float4*)(fc1_w + (tile * 32 + rrow) * D + cq * 4);
            *(float4*)(ws + rrow * WSTR + cq * 4) = w4;
        }
        __syncthreads();

        float ax = 0.f, ay = 0.f, az = 0.f, aw = 0.f;
        float bx = 0.f, by = 0.f, bz = 0.f, bw = 0.f;
        const float4* wp  = (const float4*)(ws + lane * WSTR);
        const float4* raP = (const float4*)(rs + bbA * D);
        const float4* rbP = (const float4*)(rs + bbB * D);
        #pragma unroll
        for (int cq = 0; cq < 50; cq++) {
            float4 wv = wp[cq];
            float4 ra = raP[cq];
            float4 rb = rbP[cq];
            ax += wv.x * ra.x; ay += wv.y * ra.y;
            az += wv.z * ra.z; aw += wv.w * ra.w;
            bx += wv.x * rb.x; by += wv.y * rb.y;
            bz += wv.z * rb.z; bw += wv.w * rb.w;
        }
        int oj = tile * 32 + lane;
        float s1v = d_s1[oj / FW];
        float fb  = fc1_b[oj];
        ks[bbA * FC1LEN + oj] = s1v * (((ax + ay) + (az + aw)) + fb);
        ks[bbB * FC1LEN + oj] = s1v * (((bx + by) + (bz + bw)) + fb);
        __syncthreads();
    }

    // ---- Phase C: z[bb] = sum_o sum_w vT[w][o] * sum_j ks[bb][o*9+j]*x[bb][w+j]
    float ka[FW], kb[FW];
    #pragma unroll
    for (int j = 0; j < FW; j++) {
        ka[j] = ks[bbA * FC1LEN + lane * FW + j];
        kb[j] = ks[bbB * FC1LEN + lane * FW + j];
    }
    const float* xa = xs + bbA * XSTR;
    const float* xb = xs + bbB * XSTR;
    float z0 = 0.f, z1 = 0.f;

    for (int w = 0; w < WOUT; w += 4) {
        float4 a0 = *(const float4*)(xa + w);
        float4 a1 = *(const float4*)(xa + w + 4);
        float4 a2 = *(const float4*)(xa + w + 8);
        float4 c0 = *(const float4*)(xb + w);
        float4 c1 = *(const float4*)(xb + w + 4);
        float4 c2 = *(const float4*)(xb + w + 8);
        float A[12] = {a0.x, a0.y, a0.z, a0.w, a1.x, a1.y, a1.z, a1.w,
                       a2.x, a2.y, a2.z, a2.w};
        float Cc[12] = {c0.x, c0.y, c0.z, c0.w, c1.x, c1.y, c1.z, c1.w,
                        c2.x, c2.y, c2.z, c2.w};
        #pragma unroll
        for (int dw = 0; dw < 4; dw++) {
            float vv = d_vT[(w + dw) * OC + lane];   // coalesced 128B row
            float y0 = 0.f, y1 = 0.f;
            #pragma unroll
            for (int j = 0; j < FW; j++) {
                y0 += ka[j] * A[dw + j];
                y1 += kb[j] * Cc[dw + j];
            }
            z0 += vv * y0;
            z1 += vv * y1;
        }
    }

    // reduce 32 lanes (over o)
    #pragma unroll
    for (int off = 16; off > 0; off >>= 1) {
        z0 += __shfl_down_sync(0xffffffffu, z0, off);
        z1 += __shfl_down_sync(0xffffffffu, z1, off);
    }
    if (lane == 0) {
        float C = d_sc[2] + d_sc[3];
        float bs = bias[0];
        out[b0 + bbA] = tanhf(z0 + C) + bs;
        out[b0 + bbB] = tanhf(z1 + C) + bs;
    }
}

// ---------------------------------------------------------------------------
extern "C" void kernel_launch(void* const* d_in, const int* in_sizes, int n_in,
                              void* d_out, int out_size)
{
    const int*   e1    = (const int*)d_in[0];
    const int*   ri    = (const int*)d_in[1];
    const int*   e2    = (const int*)d_in[2];
    const float* Etab  = (const float*)d_in[3];
    const float* Rtab  = (const float*)d_in[4];
    const float* g0    = (const float*)d_in[5];
    const float* b0    = (const float*)d_in[6];
    const float* m0    = (const float*)d_in[7];
    const float* v0    = (const float*)d_in[8];
    const float* fc1_w = (const float*)d_in[9];
    const float* fc1_b = (const float*)d_in[10];
    const float* g1    = (const float*)d_in[11];
    const float* b1    = (const float*)d_in[12];
    const float* m1    = (const float*)d_in[13];
    const float* v1    = (const float*)d_in[14];
    const float* fc_w  = (const float*)d_in[15];
    const float* fc_b  = (const float*)d_in[16];
    const float* g2    = (const float*)d_in[17];
    const float* b2    = (const float*)d_in[18];
    const float* m2    = (const float*)d_in[19];
    const float* v2    = (const float*)d_in[20];
    const float* fc2_w = (const float*)d_in[21];
    const float* fc2_b = (const float*)d_in[22];
    const float* bias  = (const float*)d_in[23];
    float* out = (float*)d_out;

    const int smem = (BB * XSTR + BB * 200 + 32 * WSTR + BB * FC1LEN) * 4; // 83200 B
    static int attr_done = 0;
    if (!attr_done) {
        cudaFuncSetAttribute(main_kernel, cudaFuncAttributeMaxDynamicSharedMemorySize, smem);
        attr_done = 1;
    }

    prep_g<<<1, 512>>>(fc2_w, g2, b2, m2, v2, fc_b, fc2_b,
                       g1, b1, m1, v1, g0, b0, m0, v0);
    prep_v<<<FCLEN / 256, 256>>>(fc_w);
    prep_c<<<1, 512>>>();
    main_kernel<<<BSZ / BB, 256, smem>>>(e1, ri, e2, Etab, Rtab,
                                         fc1_w, fc1_b, bias, out);
}